// round 15
// baseline (speedup 1.0000x reference)
#include <cuda_runtime.h>

// Fused transformer block. B=2048, T=128, DM=32, H=2, DK=16.
// CTA = 128 threads (4 warps), 2 batches, 2 CTAs/SM, 256 regs/thread.
// Attention: warp (b,h); lane l owns rows {l, 63-l, 64+l, 127-l} (4 rows/thread).
// Post: 64 threads x 4 batch-rows each (rows t,t+64 x 2 batches), parity-selected warps.
// Packed fma.rn.f32x2 throughout. grid = 1024.

typedef unsigned long long u64;

namespace {
constexpr int Bsz = 2048;
constexpr int T   = 128;
constexpr int DM  = 32;
constexpr int KVS = 36;    // K/V row stride (floats)
constexpr int AST = 132;   // row-group stride: 32 cols * 4 slots + 4 pad (528B, 16B-aligned)

constexpr int OFF_A  = 0;       // 4096: phase A = Wq|Wk|Wv (3072), phase B = W1 (4096)
constexpr int OFF_W2 = 4096;    // 4096
constexpr int OFF_WO = 8192;    // 1024
constexpr int OFF_B  = 9216;    // 320
constexpr int OFF_KV = 9536;    // 2 batches * (K 4608 + V 4608) = 18432
constexpr int OFF_AF = OFF_KV;           // attn buffer: 64*132 = 8448 (aliases dead K/V)
constexpr int OFF_X2 = OFF_KV + 8448;    // x2 buffer: 8448 (total 16896 < 18432)
constexpr int SMEM_FLOATS = OFF_KV + 2 * 2 * T * KVS;   // 27968
constexpr int SMEM_BYTES  = SMEM_FLOATS * 4;            // 111872 -> 2 CTAs/SM
}

__device__ __forceinline__ void ffma2(u64& acc, u64 a, u64 b) {
    asm("fma.rn.f32x2 %0, %1, %2, %0;" : "+l"(acc) : "l"(a), "l"(b));
}
__device__ __forceinline__ void fadd2(u64& a, u64 b) {
    asm("add.rn.f32x2 %0, %0, %1;" : "+l"(a) : "l"(b));
}
__device__ __forceinline__ u64 bcast2(float x) {
    u64 r; unsigned xi = __float_as_uint(x);
    asm("mov.b64 %0, {%1, %1};" : "=l"(r) : "r"(xi));
    return r;
}
__device__ __forceinline__ u64 pk2(float lo, float hi) {
    u64 r; unsigned a = __float_as_uint(lo), b = __float_as_uint(hi);
    asm("mov.b64 %0, {%1, %2};" : "=l"(r) : "r"(a), "r"(b));
    return r;
}
__device__ __forceinline__ float2 unpk(u64 v) {
    unsigned lo, hi;
    asm("mov.b64 {%0, %1}, %2;" : "=r"(lo), "=r"(hi) : "l"(v));
    return make_float2(__uint_as_float(lo), __uint_as_float(hi));
}

__device__ __forceinline__ void ln_row(float* x, const float* g, const float* be) {
    float mu = 0.f;
    #pragma unroll
    for (int d = 0; d < DM; d++) mu += x[d];
    mu *= (1.f / DM);
    float var = 0.f;
    #pragma unroll
    for (int d = 0; d < DM; d++) { float c = x[d] - mu; var = fmaf(c, c, var); }
    var *= (1.f / DM);
    float r = rsqrtf(var + 1e-5f);
    #pragma unroll
    for (int d = 0; d < DM; d++) x[d] = (x[d] - mu) * r * g[d] + be[d];
}

// one-head projection for 4 rows: W is [32 d][16 j]
__device__ __forceinline__ void proj4(const float* __restrict__ W,
                                      const float xr[4][DM], u64 o[4][8]) {
    #pragma unroll 4
    for (int d = 0; d < 32; d++) {
        u64 m0 = bcast2(xr[0][d]), m1 = bcast2(xr[1][d]);
        u64 m2 = bcast2(xr[2][d]), m3 = bcast2(xr[3][d]);
        const ulonglong2* wp = (const ulonglong2*)(W + d * 16);
        #pragma unroll
        for (int t = 0; t < 4; t++) {
            ulonglong2 wv = wp[t];
            ffma2(o[0][2*t], m0, wv.x); ffma2(o[0][2*t+1], m0, wv.y);
            ffma2(o[1][2*t], m1, wv.x); ffma2(o[1][2*t+1], m1, wv.y);
            ffma2(o[2][2*t], m2, wv.x); ffma2(o[2][2*t+1], m2, wv.y);
            ffma2(o[3][2*t], m3, wv.x); ffma2(o[3][2*t+1], m3, wv.y);
        }
    }
}

// 16-dim dot: packed accumulate, pair-add reduce, one unpack
__device__ __forceinline__ float dot8r(const u64* q2, const ulonglong2* kv) {
    u64 s0 = 0, s1 = 0;
    #pragma unroll
    for (int t = 0; t < 4; t++) { ffma2(s0, q2[2*t], kv[t].x); ffma2(s1, q2[2*t+1], kv[t].y); }
    fadd2(s0, s1);
    float2 a = unpk(s0);
    return a.x + a.y;
}

__global__ void __launch_bounds__(128, 2) block_kernel(
    const float* __restrict__ gx,
    const float* __restrict__ gWq, const float* __restrict__ gWk, const float* __restrict__ gWv,
    const float* __restrict__ gWo, const float* __restrict__ gbo,
    const float* __restrict__ gW1, const float* __restrict__ gb1,
    const float* __restrict__ gW2, const float* __restrict__ gb2,
    const float* __restrict__ gg1, const float* __restrict__ gbe1,
    const float* __restrict__ gg2, const float* __restrict__ gbe2,
    float* __restrict__ gout)
{
    extern __shared__ float sm[];
    float* sA    = sm + OFF_A;
    float* sW2   = sm + OFF_W2;
    float* sWo   = sm + OFF_WO;
    float* sbo   = sm + OFF_B;
    float* sb1   = sm + OFF_B + 32;
    float* sb2   = sm + OFF_B + 160;
    float* sg1   = sm + OFF_B + 192;
    float* sbe1  = sm + OFF_B + 224;
    float* sg2   = sm + OFF_B + 256;
    float* sbe2  = sm + OFF_B + 288;

    const int tid  = threadIdx.x;
    const int wid  = tid >> 5;
    const int lane = tid & 31;
    const int b    = wid >> 1;            // local batch 0/1
    const int h    = wid & 1;             // head 0/1
    const long gb  = (long)blockIdx.x * 2 + b;

    // 4 rows of this thread
    const int R0 = lane, R1 = 63 - lane, R2 = 64 + lane, R3 = 127 - lane;

    float* sK = sm + OFF_KV + b * (2 * T * KVS);
    float* sV = sK + T * KVS;

    // ---- phase A: cooperative weight loads ----
    {
        float4*       dq = (float4*)sA;
        const float4* s;
        s = (const float4*)gWq; for (int i = tid; i < 256;  i += 128) dq[i]       = s[i];
        s = (const float4*)gWk; for (int i = tid; i < 256;  i += 128) dq[256 + i] = s[i];
        s = (const float4*)gWv; for (int i = tid; i < 256;  i += 128) dq[512 + i] = s[i];
        float4* d2 = (float4*)sW2; s = (const float4*)gW2; for (int i = tid; i < 1024; i += 128) d2[i] = s[i];
        float4* d3 = (float4*)sWo; s = (const float4*)gWo; for (int i = tid; i < 256;  i += 128) d3[i] = s[i];
        if (tid < 32) {
            sbo[tid]  = gbo[tid];  sb2[tid]  = gb2[tid];
            sg1[tid]  = gg1[tid];  sbe1[tid] = gbe1[tid];
            sg2[tid]  = gg2[tid];  sbe2[tid] = gbe2[tid];
        }
        sb1[tid] = gb1[tid];
    }
    __syncthreads();

    // ---- x rows (4) + LN1 ----
    float xr[4][DM];
    {
        const int R[4] = {R0, R1, R2, R3};
        #pragma unroll
        for (int r = 0; r < 4; r++) {
            const float4* pr = (const float4*)(gx + (gb * T + R[r]) * DM);
            #pragma unroll
            for (int i = 0; i < 8; i++) {
                float4 v = pr[i];
                xr[r][4*i] = v.x; xr[r][4*i+1] = v.y; xr[r][4*i+2] = v.z; xr[r][4*i+3] = v.w;
            }
            ln_row(xr[r], sg1, sbe1);
        }
    }

    // ---- head-h projections for 4 rows: k, v -> smem; q kept live ----
    {
        u64 kk[4][8];
        #pragma unroll
        for (int r = 0; r < 4; r++)
            #pragma unroll
            for (int p = 0; p < 8; p++) kk[r][p] = 0;
        proj4(sA + 1024 + h * 512, xr, kk);
        const int R[4] = {R0, R1, R2, R3};
        #pragma unroll
        for (int r = 0; r < 4; r++) {
            u64* kr = (u64*)(sK + R[r] * KVS + h * 16);
            #pragma unroll
            for (int p = 0; p < 8; p++) kr[p] = kk[r][p];
        }
    }
    {
        u64 vv4[4][8];
        #pragma unroll
        for (int r = 0; r < 4; r++)
            #pragma unroll
            for (int p = 0; p < 8; p++) vv4[r][p] = 0;
        proj4(sA + 2048 + h * 512, xr, vv4);
        const int R[4] = {R0, R1, R2, R3};
        #pragma unroll
        for (int r = 0; r < 4; r++) {
            u64* vr = (u64*)(sV + R[r] * KVS + h * 16);
            #pragma unroll
            for (int p = 0; p < 8; p++) vr[p] = vv4[r][p];
        }
    }
    u64 q4[4][8];
    #pragma unroll
    for (int r = 0; r < 4; r++)
        #pragma unroll
        for (int p = 0; p < 8; p++) q4[r][p] = 0;
    proj4(sA + h * 512, xr, q4);

    __syncthreads();   // K/V visible; QKV weights dead

    // stage W1 into region A (overlaps attention)
    {
        const float4* s = (const float4*)gW1;
        float4*       d = (float4*)sA;
        #pragma unroll
        for (int i = tid; i < 1024; i += 128) d[i] = s[i];
    }

    // ---- attention: 4 rows, head h; 4 warp-uniform segments of 32 iters ----
    u64 a0[8], a1[8], a2[8], a3[8];
    #pragma unroll
    for (int p = 0; p < 8; p++) { a0[p] = 0; a1[p] = 0; a2[p] = 0; a3[p] = 0; }
    float l0 = 0.f, l1 = 0.f, l2 = 0.f, l3 = 0.f;

    const float* kh = sK + h * 16;
    const float* vh = sV + h * 16;

    // segment 0: s=0..31 — rows 0(pred),1,2,3
    for (int s = 0; s < 32; s++) {
        const ulonglong2* kp = (const ulonglong2*)(kh + s * KVS);
        ulonglong2 kv[4];
        #pragma unroll
        for (int q = 0; q < 4; q++) kv[q] = kp[q];
        float d0 = dot8r(q4[0], kv), d1 = dot8r(q4[1], kv);
        float d2 = dot8r(q4[2], kv), d3 = dot8r(q4[3], kv);
        float p0 = (s <= R0) ? __expf(d0) : 0.f;
        float p1 = __expf(d1), p2 = __expf(d2), p3 = __expf(d3);
        l0 += p0; l1 += p1; l2 += p2; l3 += p3;
        const ulonglong2* vp = (const ulonglong2*)(vh + s * KVS);
        ulonglong2 vv[4];
        #pragma unroll
        for (int q = 0; q < 4; q++) vv[q] = vp[q];
        u64 P0 = bcast2(p0), P1 = bcast2(p1), P2 = bcast2(p2), P3 = bcast2(p3);
        #pragma unroll
        for (int q = 0; q < 4; q++) {
            ffma2(a0[2*q], P0, vv[q].x); ffma2(a0[2*q+1], P0, vv[q].y);
            ffma2(a1[2*q], P1, vv[q].x); ffma2(a1[2*q+1], P1, vv[q].y);
            ffma2(a2[2*q], P2, vv[q].x); ffma2(a2[2*q+1], P2, vv[q].y);
            ffma2(a3[2*q], P3, vv[q].x); ffma2(a3[2*q+1], P3, vv[q].y);
        }
    }
    // segment 1: s=32..63 — rows 1(pred),2,3
    for (int s = 32; s < 64; s++) {
        const ulonglong2* kp = (const ulonglong2*)(kh + s * KVS);
        ulonglong2 kv[4];
        #pragma unroll
        for (int q = 0; q < 4; q++) kv[q] = kp[q];
        float d1 = dot8r(q4[1], kv), d2 = dot8r(q4[2], kv), d3 = dot8r(q4[3], kv);
        float p1 = (s <= R1) ? __expf(d1) : 0.f;
        float p2 = __expf(d2), p3 = __expf(d3);
        l1 += p1; l2 += p2; l3 += p3;
        const ulonglong2* vp = (const ulonglong2*)(vh + s * KVS);
        ulonglong2 vv[4];
        #pragma unroll
        for (int q = 0; q < 4; q++) vv[q] = vp[q];
        u64 P1 = bcast2(p1), P2 = bcast2(p2), P3 = bcast2(p3);
        #pragma unroll
        for (int q = 0; q < 4; q++) {
            ffma2(a1[2*q], P1, vv[q].x); ffma2(a1[2*q+1], P1, vv[q].y);
            ffma2(a2[2*q], P2, vv[q].x); ffma2(a2[2*q+1], P2, vv[q].y);
            ffma2(a3[2*q], P3, vv[q].x); ffma2(a3[2*q+1], P3, vv[q].y);
        }
    }
    // segment 2: s=64..95 — rows 2(pred),3
    for (int s = 64; s < 96; s++) {
        const ulonglong2* kp = (const ulonglong2*)(kh + s * KVS);
        ulonglong2 kv[4];
        #pragma unroll
        for (int q = 0; q < 4; q++) kv[q] = kp[q];
        float d2 = dot8r(q4[2], kv), d3 = dot8r(q4[3], kv);
        float p2 = (s <= R2) ? __expf(d2) : 0.f;
        float p3 = __expf(d3);
        l2 += p2; l3 += p3;
        const ulonglong2* vp = (const ulonglong2*)(vh + s * KVS);
        ulonglong2 vv[4];
        #pragma unroll
        for (int q = 0; q < 4; q++) vv[q] = vp[q];
        u64 P2 = bcast2(p2), P3 = bcast2(p3);
        #pragma unroll
        for (int q = 0; q < 4; q++) {
            ffma2(a2[2*q], P2, vv[q].x); ffma2(a2[2*q+1], P2, vv[q].y);
            ffma2(a3[2*q], P3, vv[q].x); ffma2(a3[2*q+1], P3, vv[q].y);
        }
    }
    // segment 3: s=96..127 — row 3(pred)
    for (int s = 96; s < 128; s++) {
        const ulonglong2* kp = (const ulonglong2*)(kh + s * KVS);
        ulonglong2 kv[4];
        #pragma unroll
        for (int q = 0; q < 4; q++) kv[q] = kp[q];
        float d3 = dot8r(q4[3], kv);
        float p3 = (s <= R3) ? __expf(d3) : 0.f;
        l3 += p3;
        const ulonglong2* vp = (const ulonglong2*)(vh + s * KVS);
        u64 P3 = bcast2(p3);
        #pragma unroll
        for (int q = 0; q < 4; q++) {
            ulonglong2 vv = vp[q];
            ffma2(a3[2*q], P3, vv.x); ffma2(a3[2*q+1], P3, vv.y);
        }
    }

    __syncthreads();   // all K/V reads done; region becomes attn buffer

    // ---- store normalized attn: attnF[(R&63)*AST + j*4 + slot], slot=((R>>6)<<1)|b ----
    {
        const int R[4] = {R0, R1, R2, R3};
        u64* accs[4] = {a0, a1, a2, a3};
        float invs[4] = {1.f / l0, 1.f / l1, 1.f / l2, 1.f / l3};
        #pragma unroll
        for (int r = 0; r < 4; r++) {
            float* base = sm + OFF_AF + (R[r] & 63) * AST + (((R[r] >> 6) << 1) | b);
            float iv = invs[r];
            #pragma unroll
            for (int p = 0; p < 8; p++) {
                int j0 = 16 * h + 2 * p;
                float2 f = unpk(accs[r][p]);
                base[j0 * 4]       = f.x * iv;
                base[(j0 + 1) * 4] = f.y * iv;
            }
        }
    }
    __syncthreads();

    // ==== post phase: parity-selected warp pair, 64 threads x 4 batch-rows ====
    const int pw = (blockIdx.x & 1) << 1;            // even CTA: warps 0,1; odd: 2,3
    if (wid != pw && wid != pw + 1) return;
    const int pt = tid - (pw << 5);                  // 0..63
    const long gB0 = (long)blockIdx.x * 2, gB1 = gB0 + 1;
    float* afr = sm + OFF_AF + pt * AST;
    float* x2r = sm + OFF_X2 + pt * AST;

    // Wo accumulators init with residual LN1(x) + bo; i = (rowhi<<1)|batch
    u64 o[4][16];
    #pragma unroll
    for (int i = 0; i < 4; i++) {
        const int  row  = pt + ((i >> 1) << 6);
        const long gbat = (i & 1) ? gB1 : gB0;
        float xt[DM];
        const float4* pr = (const float4*)(gx + (gbat * T + row) * DM);
        #pragma unroll
        for (int k = 0; k < 8; k++) {
            float4 v = pr[k];
            xt[4*k] = v.x; xt[4*k+1] = v.y; xt[4*k+2] = v.z; xt[4*k+3] = v.w;
        }
        ln_row(xt, sg1, sbe1);
        #pragma unroll
        for (int p = 0; p < 16; p++)
            o[i][p] = pk2(xt[2*p] + sbo[2*p], xt[2*p+1] + sbo[2*p+1]);
    }

    // attn @ Wo: one LDS.128 yields all 4 multipliers; each Wo load feeds 8 FFMA2
    #pragma unroll 2
    for (int e = 0; e < 32; e++) {
        float4 ap = *(const float4*)(afr + e * 4);
        u64 m0 = bcast2(ap.x), m1 = bcast2(ap.y), m2 = bcast2(ap.z), m3 = bcast2(ap.w);
        const ulonglong2* wp = (const ulonglong2*)(sWo + e * 32);
        #pragma unroll
        for (int q = 0; q < 8; q++) {
            ulonglong2 wv = wp[q];
            ffma2(o[0][2*q], m0, wv.x); ffma2(o[0][2*q+1], m0, wv.y);
            ffma2(o[1][2*q], m1, wv.x); ffma2(o[1][2*q+1], m1, wv.y);
            ffma2(o[2][2*q], m2, wv.x); ffma2(o[2][2*q+1], m2, wv.y);
            ffma2(o[3][2*q], m3, wv.x); ffma2(o[3][2*q+1], m3, wv.y);
        }
    }

    // LN2 per batch-row; x2 -> smem (self-read only); FFN residual accum init
    u64 r2[4][16];
    #pragma unroll
    for (int i = 0; i < 4; i++) {
        float xx[DM];
        #pragma unroll
        for (int p = 0; p < 16; p++) {
            float2 f = unpk(o[i][p]); xx[2*p] = f.x; xx[2*p+1] = f.y;
        }
        ln_row(xx, sg2, sbe2);
        #pragma unroll
        for (int d = 0; d < DM; d++) x2r[d * 4 + i] = xx[d];
        #pragma unroll
        for (int p = 0; p < 16; p++)
            r2[i][p] = pk2(xx[2*p] + sb2[2*p], xx[2*p+1] + sb2[2*p+1]);
    }

    // ---- FFN: hidden blocks of 16; each W1/W2 load feeds 8 FFMA2 ----
    #pragma unroll 1
    for (int blk = 0; blk < 8; blk++) {
        const float* w1p = sA + blk * 16;
        u64 hh[4][8];
        #pragma unroll
        for (int i = 0; i < 4; i++)
            #pragma unroll
            for (int p = 0; p < 8; p++) hh[i][p] = 0;
        #pragma unroll 2
        for (int d = 0; d < 32; d++) {
            float4 xp = *(const float4*)(x2r + d * 4);
            u64 m0 = bcast2(xp.x), m1 = bcast2(xp.y), m2 = bcast2(xp.z), m3 = bcast2(xp.w);
            const ulonglong2* wp = (const ulonglong2*)(w1p + d * 128);
            #pragma unroll
            for (int t = 0; t < 4; t++) {
                ulonglong2 wv = wp[t];
                ffma2(hh[0][2*t], m0, wv.x); ffma2(hh[0][2*t+1], m0, wv.y);
                ffma2(hh[1][2*t], m1, wv.x); ffma2(hh[1][2*t+1], m1, wv.y);
                ffma2(hh[2][2*t], m2, wv.x); ffma2(hh[2][2*t+1], m2, wv.y);
                ffma2(hh[3][2*t], m3, wv.x); ffma2(hh[3][2*t+1], m3, wv.y);
            }
        }
        #pragma unroll
        for (int p = 0; p < 8; p++) {
            const int j = blk * 16 + 2 * p;
            float A0[4], A1[4];
            #pragma unroll
            for (int i = 0; i < 4; i++) {
                float2 f = unpk(hh[i][p]);
                A0[i] = fmaxf(f.x + sb1[j],     0.f);
                A1[i] = fmaxf(f.y + sb1[j + 1], 0.f);
            }
            {
                u64 P0 = bcast2(A0[0]), P1 = bcast2(A0[1]), P2 = bcast2(A0[2]), P3 = bcast2(A0[3]);
                const ulonglong2* w2 = (const ulonglong2*)(sW2 + j * 32);
                #pragma unroll
                for (int q = 0; q < 8; q++) {
                    ulonglong2 wv = w2[q];
                    ffma2(r2[0][2*q], P0, wv.x); ffma2(r2[0][2*q+1], P0, wv.y);
                    ffma2(r2[1][2*q], P1, wv.x); ffma2(r2[1][2*q+1], P1, wv.y);
                    ffma2(r2[2][2*q], P2, wv.x); ffma2(r2[2][2*q+1], P2, wv.y);
                    ffma2(r2[3][2*q], P3, wv.x); ffma2(r2[3][2*q+1], P3, wv.y);
                }
            }
            {
                u64 P0 = bcast2(A1[0]), P1 = bcast2(A1[1]), P2 = bcast2(A1[2]), P3 = bcast2(A1[3]);
                const ulonglong2* w2 = (const ulonglong2*)(sW2 + (j + 1) * 32);
                #pragma unroll
                for (int q = 0; q < 8; q++) {
                    ulonglong2 wv = w2[q];
                    ffma2(r2[0][2*q], P0, wv.x); ffma2(r2[0][2*q+1], P0, wv.y);
                    ffma2(r2[1][2*q], P1, wv.x); ffma2(r2[1][2*q+1], P1, wv.y);
                    ffma2(r2[2][2*q], P2, wv.x); ffma2(r2[2][2*q+1], P2, wv.y);
                    ffma2(r2[3][2*q], P3, wv.x); ffma2(r2[3][2*q+1], P3, wv.y);
                }
            }
        }
    }

    // ---- store 4 batch-rows ----
    #pragma unroll
    for (int i = 0; i < 4; i++) {
        const int  row  = pt + ((i >> 1) << 6);
        const long gbat = (i & 1) ? gB1 : gB0;
        ulonglong2* op = (ulonglong2*)(gout + (gbat * T + row) * DM);
        #pragma unroll
        for (int q = 0; q < 8; q++) op[q] = make_ulonglong2(r2[i][2*q], r2[i][2*q+1]);
    }
}

extern "C" void kernel_launch(void* const* d_in, const int* in_sizes, int n_in,
                              void* d_out, int out_size)
{
    const float* x   = (const float*)d_in[0];
    const float* Wq  = (const float*)d_in[1];
    const float* Wk  = (const float*)d_in[2];
    const float* Wv  = (const float*)d_in[3];
    const float* Wo  = (const float*)d_in[4];
    const float* bo  = (const float*)d_in[5];
    const float* W1  = (const float*)d_in[6];
    const float* b1  = (const float*)d_in[7];
    const float* W2  = (const float*)d_in[8];
    const float* b2  = (const float*)d_in[9];
    const float* g1  = (const float*)d_in[10];
    const float* be1 = (const float*)d_in[11];
    const float* g2  = (const float*)d_in[12];
    const float* be2 = (const float*)d_in[13];
    float* out = (float*)d_out;

    cudaFuncSetAttribute(block_kernel, cudaFuncAttributeMaxDynamicSharedMemorySize, SMEM_BYTES);
    block_kernel<<<Bsz / 2, 128, SMEM_BYTES>>>(x, Wq, Wk, Wv, Wo, bo, W1, b1, W2, b2,
                                               g1, be1, g2, be2, out);
}

// round 16
// speedup vs baseline: 1.2969x; 1.2969x over previous
#include <cuda_runtime.h>

// Fused transformer block. B=2048, T=128, DM=32, H=2, DK=16.
// CTA = 128 threads (4 warps), 2 batches, 2 CTAs/SM.
// Attention: warp (b,h); lane l owns rows {l, 63-l, 64+l, 127-l} (4 rows/thread, 4 segments).
// Post: all 128 threads; thread t owns row t of BOTH batches (R13-style interleaved pairs).
// Packed fma.rn.f32x2 throughout. grid = 1024.

typedef unsigned long long u64;

namespace {
constexpr int Bsz = 2048;
constexpr int T   = 128;
constexpr int DM  = 32;
constexpr int KVS = 36;    // K/V row stride (floats)
constexpr int AST = 66;    // attn/x2 interleaved buffer row stride (floats): 64 data + 2 pad

constexpr int OFF_A  = 0;       // 4096: phase A = Wq|Wk|Wv (3072), phase B = W1 (4096)
constexpr int OFF_W2 = 4096;    // 4096
constexpr int OFF_WO = 8192;    // 1024
constexpr int OFF_B  = 9216;    // 320
constexpr int OFF_KV = 9536;    // 2 batches * (K 4608 + V 4608) = 18432; attnF (128*66=8448) aliases
constexpr int SMEM_FLOATS = OFF_KV + 2 * 2 * T * KVS;   // 27968
constexpr int SMEM_BYTES  = SMEM_FLOATS * 4;            // 111872 -> 2 CTAs/SM
}

__device__ __forceinline__ void ffma2(u64& acc, u64 a, u64 b) {
    asm("fma.rn.f32x2 %0, %1, %2, %0;" : "+l"(acc) : "l"(a), "l"(b));
}
__device__ __forceinline__ void fadd2(u64& a, u64 b) {
    asm("add.rn.f32x2 %0, %0, %1;" : "+l"(a) : "l"(b));
}
__device__ __forceinline__ u64 bcast2(float x) {
    u64 r; unsigned xi = __float_as_uint(x);
    asm("mov.b64 %0, {%1, %1};" : "=l"(r) : "r"(xi));
    return r;
}
__device__ __forceinline__ u64 pk2(float lo, float hi) {
    u64 r; unsigned a = __float_as_uint(lo), b = __float_as_uint(hi);
    asm("mov.b64 %0, {%1, %2};" : "=l"(r) : "r"(a), "r"(b));
    return r;
}
__device__ __forceinline__ float2 unpk(u64 v) {
    unsigned lo, hi;
    asm("mov.b64 {%0, %1}, %2;" : "=r"(lo), "=r"(hi) : "l"(v));
    return make_float2(__uint_as_float(lo), __uint_as_float(hi));
}
__device__ __forceinline__ void split_bcast(u64 v, u64& m0, u64& m1) {
    unsigned lo, hi;
    asm("mov.b64 {%0, %1}, %2;" : "=r"(lo), "=r"(hi) : "l"(v));
    asm("mov.b64 %0, {%1, %1};" : "=l"(m0) : "r"(lo));
    asm("mov.b64 %0, {%1, %1};" : "=l"(m1) : "r"(hi));
}

__device__ __forceinline__ void ln_row(float* x, const float* g, const float* be) {
    float mu = 0.f;
    #pragma unroll
    for (int d = 0; d < DM; d++) mu += x[d];
    mu *= (1.f / DM);
    float var = 0.f;
    #pragma unroll
    for (int d = 0; d < DM; d++) { float c = x[d] - mu; var = fmaf(c, c, var); }
    var *= (1.f / DM);
    float r = rsqrtf(var + 1e-5f);
    #pragma unroll
    for (int d = 0; d < DM; d++) x[d] = (x[d] - mu) * r * g[d] + be[d];
}

// one-head projection for 4 rows: W is [32 d][16 j]
__device__ __forceinline__ void proj4(const float* __restrict__ W,
                                      const float xr[4][DM], u64 o[4][8]) {
    #pragma unroll 4
    for (int d = 0; d < 32; d++) {
        u64 m0 = bcast2(xr[0][d]), m1 = bcast2(xr[1][d]);
        u64 m2 = bcast2(xr[2][d]), m3 = bcast2(xr[3][d]);
        const ulonglong2* wp = (const ulonglong2*)(W + d * 16);
        #pragma unroll
        for (int t = 0; t < 4; t++) {
            ulonglong2 wv = wp[t];
            ffma2(o[0][2*t], m0, wv.x); ffma2(o[0][2*t+1], m0, wv.y);
            ffma2(o[1][2*t], m1, wv.x); ffma2(o[1][2*t+1], m1, wv.y);
            ffma2(o[2][2*t], m2, wv.x); ffma2(o[2][2*t+1], m2, wv.y);
            ffma2(o[3][2*t], m3, wv.x); ffma2(o[3][2*t+1], m3, wv.y);
        }
    }
}

// 16-dim dot: packed accumulate, pair-add reduce, one unpack
__device__ __forceinline__ float dot8r(const u64* q2, const ulonglong2* kv) {
    u64 s0 = 0, s1 = 0;
    #pragma unroll
    for (int t = 0; t < 4; t++) { ffma2(s0, q2[2*t], kv[t].x); ffma2(s1, q2[2*t+1], kv[t].y); }
    fadd2(s0, s1);
    float2 a = unpk(s0);
    return a.x + a.y;
}

__global__ void __launch_bounds__(128, 2) block_kernel(
    const float* __restrict__ gx,
    const float* __restrict__ gWq, const float* __restrict__ gWk, const float* __restrict__ gWv,
    const float* __restrict__ gWo, const float* __restrict__ gbo,
    const float* __restrict__ gW1, const float* __restrict__ gb1,
    const float* __restrict__ gW2, const float* __restrict__ gb2,
    const float* __restrict__ gg1, const float* __restrict__ gbe1,
    const float* __restrict__ gg2, const float* __restrict__ gbe2,
    float* __restrict__ gout)
{
    extern __shared__ float sm[];
    float* sA    = sm + OFF_A;
    float* sW2   = sm + OFF_W2;
    float* sWo   = sm + OFF_WO;
    float* sbo   = sm + OFF_B;
    float* sb1   = sm + OFF_B + 32;
    float* sb2   = sm + OFF_B + 160;
    float* sg1   = sm + OFF_B + 192;
    float* sbe1  = sm + OFF_B + 224;
    float* sg2   = sm + OFF_B + 256;
    float* sbe2  = sm + OFF_B + 288;
    float* attnF = sm + OFF_KV;     // post phases: interleaved attn/x2 rows, 128 x AST

    const int tid  = threadIdx.x;
    const int wid  = tid >> 5;
    const int lane = tid & 31;
    const int b    = wid >> 1;            // local batch 0/1
    const int h    = wid & 1;             // head 0/1
    const long gb  = (long)blockIdx.x * 2 + b;

    // 4 rows of this thread
    const int R0 = lane, R1 = 63 - lane, R2 = 64 + lane, R3 = 127 - lane;

    float* sK = sm + OFF_KV + b * (2 * T * KVS);
    float* sV = sK + T * KVS;

    // ---- phase A: cooperative weight loads ----
    {
        float4*       dq = (float4*)sA;
        const float4* s;
        s = (const float4*)gWq; for (int i = tid; i < 256;  i += 128) dq[i]       = s[i];
        s = (const float4*)gWk; for (int i = tid; i < 256;  i += 128) dq[256 + i] = s[i];
        s = (const float4*)gWv; for (int i = tid; i < 256;  i += 128) dq[512 + i] = s[i];
        float4* d2 = (float4*)sW2; s = (const float4*)gW2; for (int i = tid; i < 1024; i += 128) d2[i] = s[i];
        float4* d3 = (float4*)sWo; s = (const float4*)gWo; for (int i = tid; i < 256;  i += 128) d3[i] = s[i];
        if (tid < 32) {
            sbo[tid]  = gbo[tid];  sb2[tid]  = gb2[tid];
            sg1[tid]  = gg1[tid];  sbe1[tid] = gbe1[tid];
            sg2[tid]  = gg2[tid];  sbe2[tid] = gbe2[tid];
        }
        sb1[tid] = gb1[tid];
    }
    __syncthreads();

    // ---- x rows (4) + LN1 ----
    float xr[4][DM];
    {
        const int R[4] = {R0, R1, R2, R3};
        #pragma unroll
        for (int r = 0; r < 4; r++) {
            const float4* pr = (const float4*)(gx + (gb * T + R[r]) * DM);
            #pragma unroll
            for (int i = 0; i < 8; i++) {
                float4 v = pr[i];
                xr[r][4*i] = v.x; xr[r][4*i+1] = v.y; xr[r][4*i+2] = v.z; xr[r][4*i+3] = v.w;
            }
            ln_row(xr[r], sg1, sbe1);
        }
    }

    // ---- head-h projections for 4 rows: k, v -> smem; q kept live ----
    {
        u64 kk[4][8];
        #pragma unroll
        for (int r = 0; r < 4; r++)
            #pragma unroll
            for (int p = 0; p < 8; p++) kk[r][p] = 0;
        proj4(sA + 1024 + h * 512, xr, kk);
        const int R[4] = {R0, R1, R2, R3};
        #pragma unroll
        for (int r = 0; r < 4; r++) {
            u64* kr = (u64*)(sK + R[r] * KVS + h * 16);
            #pragma unroll
            for (int p = 0; p < 8; p++) kr[p] = kk[r][p];
        }
    }
    {
        u64 vv4[4][8];
        #pragma unroll
        for (int r = 0; r < 4; r++)
            #pragma unroll
            for (int p = 0; p < 8; p++) vv4[r][p] = 0;
        proj4(sA + 2048 + h * 512, xr, vv4);
        const int R[4] = {R0, R1, R2, R3};
        #pragma unroll
        for (int r = 0; r < 4; r++) {
            u64* vr = (u64*)(sV + R[r] * KVS + h * 16);
            #pragma unroll
            for (int p = 0; p < 8; p++) vr[p] = vv4[r][p];
        }
    }
    u64 q4[4][8];
    #pragma unroll
    for (int r = 0; r < 4; r++)
        #pragma unroll
        for (int p = 0; p < 8; p++) q4[r][p] = 0;
    proj4(sA + h * 512, xr, q4);

    __syncthreads();   // K/V visible; QKV weights dead

    // stage W1 into region A (overlaps attention)
    {
        const float4* s = (const float4*)gW1;
        float4*       d = (float4*)sA;
        #pragma unroll
        for (int i = tid; i < 1024; i += 128) d[i] = s[i];
    }

    // ---- attention: 4 rows, head h; 4 warp-uniform segments of 32 iters ----
    u64 a0[8], a1[8], a2[8], a3[8];
    #pragma unroll
    for (int p = 0; p < 8; p++) { a0[p] = 0; a1[p] = 0; a2[p] = 0; a3[p] = 0; }
    float l0 = 0.f, l1 = 0.f, l2 = 0.f, l3 = 0.f;

    const float* kh = sK + h * 16;
    const float* vh = sV + h * 16;

    // segment 0: s=0..31 — rows 0(pred),1,2,3
    for (int s = 0; s < 32; s++) {
        const ulonglong2* kp = (const ulonglong2*)(kh + s * KVS);
        ulonglong2 kv[4];
        #pragma unroll
        for (int q = 0; q < 4; q++) kv[q] = kp[q];
        float d0 = dot8r(q4[0], kv), d1 = dot8r(q4[1], kv);
        float d2 = dot8r(q4[2], kv), d3 = dot8r(q4[3], kv);
        float p0 = (s <= R0) ? __expf(d0) : 0.f;
        float p1 = __expf(d1), p2 = __expf(d2), p3 = __expf(d3);
        l0 += p0; l1 += p1; l2 += p2; l3 += p3;
        const ulonglong2* vp = (const ulonglong2*)(vh + s * KVS);
        ulonglong2 vv[4];
        #pragma unroll
        for (int q = 0; q < 4; q++) vv[q] = vp[q];
        u64 P0 = bcast2(p0), P1 = bcast2(p1), P2 = bcast2(p2), P3 = bcast2(p3);
        #pragma unroll
        for (int q = 0; q < 4; q++) {
            ffma2(a0[2*q], P0, vv[q].x); ffma2(a0[2*q+1], P0, vv[q].y);
            ffma2(a1[2*q], P1, vv[q].x); ffma2(a1[2*q+1], P1, vv[q].y);
            ffma2(a2[2*q], P2, vv[q].x); ffma2(a2[2*q+1], P2, vv[q].y);
            ffma2(a3[2*q], P3, vv[q].x); ffma2(a3[2*q+1], P3, vv[q].y);
        }
    }
    // segment 1: s=32..63 — rows 1(pred),2,3
    for (int s = 32; s < 64; s++) {
        const ulonglong2* kp = (const ulonglong2*)(kh + s * KVS);
        ulonglong2 kv[4];
        #pragma unroll
        for (int q = 0; q < 4; q++) kv[q] = kp[q];
        float d1 = dot8r(q4[1], kv), d2 = dot8r(q4[2], kv), d3 = dot8r(q4[3], kv);
        float p1 = (s <= R1) ? __expf(d1) : 0.f;
        float p2 = __expf(d2), p3 = __expf(d3);
        l1 += p1; l2 += p2; l3 += p3;
        const ulonglong2* vp = (const ulonglong2*)(vh + s * KVS);
        ulonglong2 vv[4];
        #pragma unroll
        for (int q = 0; q < 4; q++) vv[q] = vp[q];
        u64 P1 = bcast2(p1), P2 = bcast2(p2), P3 = bcast2(p3);
        #pragma unroll
        for (int q = 0; q < 4; q++) {
            ffma2(a1[2*q], P1, vv[q].x); ffma2(a1[2*q+1], P1, vv[q].y);
            ffma2(a2[2*q], P2, vv[q].x); ffma2(a2[2*q+1], P2, vv[q].y);
            ffma2(a3[2*q], P3, vv[q].x); ffma2(a3[2*q+1], P3, vv[q].y);
        }
    }
    // segment 2: s=64..95 — rows 2(pred),3
    for (int s = 64; s < 96; s++) {
        const ulonglong2* kp = (const ulonglong2*)(kh + s * KVS);
        ulonglong2 kv[4];
        #pragma unroll
        for (int q = 0; q < 4; q++) kv[q] = kp[q];
        float d2 = dot8r(q4[2], kv), d3 = dot8r(q4[3], kv);
        float p2 = (s <= R2) ? __expf(d2) : 0.f;
        float p3 = __expf(d3);
        l2 += p2; l3 += p3;
        const ulonglong2* vp = (const ulonglong2*)(vh + s * KVS);
        ulonglong2 vv[4];
        #pragma unroll
        for (int q = 0; q < 4; q++) vv[q] = vp[q];
        u64 P2 = bcast2(p2), P3 = bcast2(p3);
        #pragma unroll
        for (int q = 0; q < 4; q++) {
            ffma2(a2[2*q], P2, vv[q].x); ffma2(a2[2*q+1], P2, vv[q].y);
            ffma2(a3[2*q], P3, vv[q].x); ffma2(a3[2*q+1], P3, vv[q].y);
        }
    }
    // segment 3: s=96..127 — row 3(pred)
    for (int s = 96; s < 128; s++) {
        const ulonglong2* kp = (const ulonglong2*)(kh + s * KVS);
        ulonglong2 kv[4];
        #pragma unroll
        for (int q = 0; q < 4; q++) kv[q] = kp[q];
        float d3 = dot8r(q4[3], kv);
        float p3 = (s <= R3) ? __expf(d3) : 0.f;
        l3 += p3;
        const ulonglong2* vp = (const ulonglong2*)(vh + s * KVS);
        u64 P3 = bcast2(p3);
        #pragma unroll
        for (int q = 0; q < 4; q++) {
            ulonglong2 vv = vp[q];
            ffma2(a3[2*q], P3, vv.x); ffma2(a3[2*q+1], P3, vv.y);
        }
    }

    __syncthreads();   // all K/V reads done; region becomes interleaved attn buffer

    // ---- store normalized attn (R13 format): attnF[R*AST + 2*j + b] ----
    {
        const int R[4] = {R0, R1, R2, R3};
        u64* accs[4] = {a0, a1, a2, a3};
        float invs[4] = {1.f / l0, 1.f / l1, 1.f / l2, 1.f / l3};
        #pragma unroll
        for (int r = 0; r < 4; r++) {
            float* base = attnF + R[r] * AST + b;
            float iv = invs[r];
            #pragma unroll
            for (int p = 0; p < 8; p++) {
                int j0 = 16 * h + 2 * p;
                float2 f = unpk(accs[r][p]);
                base[2 * j0]       = f.x * iv;
                base[2 * (j0 + 1)] = f.y * iv;
            }
        }
    }
    __syncthreads();

    // ==== post-attention (R13): all 128 threads, row t for BOTH batches ====
    const int t = tid;
    const long gB0 = (long)blockIdx.x * 2;
    const long gB1 = gB0 + 1;

    // Wo accumulators initialized with residual LN1(x) + bo
    u64 oA[16], oB[16];
    {
        float xA[DM], xB[DM];
        const float4* p0 = (const float4*)(gx + (gB0 * T + t) * DM);
        const float4* p1 = (const float4*)(gx + (gB1 * T + t) * DM);
        #pragma unroll
        for (int i = 0; i < 8; i++) {
            float4 v = p0[i]; xA[4*i] = v.x; xA[4*i+1] = v.y; xA[4*i+2] = v.z; xA[4*i+3] = v.w;
            float4 w = p1[i]; xB[4*i] = w.x; xB[4*i+1] = w.y; xB[4*i+2] = w.z; xB[4*i+3] = w.w;
        }
        ln_row(xA, sg1, sbe1);
        ln_row(xB, sg1, sbe1);
        #pragma unroll
        for (int p = 0; p < 16; p++) {
            oA[p] = pk2(xA[2*p] + sbo[2*p], xA[2*p+1] + sbo[2*p+1]);
            oB[p] = pk2(xB[2*p] + sbo[2*p], xB[2*p+1] + sbo[2*p+1]);
        }
    }

    // attn @ Wo, both batches share each Wo load
    const float* myrow = attnF + t * AST;
    #pragma unroll 4
    for (int e = 0; e < 32; e++) {
        u64 ap = *(const u64*)(myrow + 2 * e);
        u64 m0, m1; split_bcast(ap, m0, m1);
        const ulonglong2* wp = (const ulonglong2*)(sWo + e * 32);
        #pragma unroll
        for (int q = 0; q < 8; q++) {
            ulonglong2 wv = wp[q];
            ffma2(oA[2*q], m0, wv.x); ffma2(oA[2*q+1], m0, wv.y);
            ffma2(oB[2*q], m1, wv.x); ffma2(oB[2*q+1], m1, wv.y);
        }
    }

    // LN2, stash x2 pairs in smem (same row, in place), init FFN residual accumulators
    u64 r2a[16], r2b[16];
    {
        float x2A[DM], x2B[DM];
        #pragma unroll
        for (int p = 0; p < 16; p++) {
            float2 f = unpk(oA[p]); x2A[2*p] = f.x; x2A[2*p+1] = f.y;
            float2 g = unpk(oB[p]); x2B[2*p] = g.x; x2B[2*p+1] = g.y;
        }
        ln_row(x2A, sg2, sbe2);
        ln_row(x2B, sg2, sbe2);
        u64* xrow = (u64*)myrow;
        #pragma unroll
        for (int d = 0; d < 32; d++) xrow[d] = pk2(x2A[d], x2B[d]);
        #pragma unroll
        for (int p = 0; p < 16; p++) {
            r2a[p] = pk2(x2A[2*p] + sb2[2*p], x2A[2*p+1] + sb2[2*p+1]);
            r2b[p] = pk2(x2B[2*p] + sb2[2*p], x2B[2*p+1] + sb2[2*p+1]);
        }
    }

    // ---- FFN: hidden in blocks of 16; x2 pairs re-read from smem; weights shared 2 rows ----
    #pragma unroll 1
    for (int blk = 0; blk < 8; blk++) {
        const float* w1p = sA + blk * 16;
        u64 h0[8], h1[8];
        #pragma unroll
        for (int p = 0; p < 8; p++) { h0[p] = 0; h1[p] = 0; }
        #pragma unroll 4
        for (int d = 0; d < 32; d++) {
            u64 xp = *(const u64*)(myrow + 2 * d);
            u64 m0, m1; split_bcast(xp, m0, m1);
            const ulonglong2* wp = (const ulonglong2*)(w1p + d * 128);
            #pragma unroll
            for (int q = 0; q < 4; q++) {
                ulonglong2 wv = wp[q];
                ffma2(h0[2*q],   m0, wv.x); ffma2(h0[2*q+1],   m0, wv.y);
                ffma2(h1[2*q],   m1, wv.x); ffma2(h1[2*q+1],   m1, wv.y);
            }
        }
        #pragma unroll
        for (int p = 0; p < 8; p++) {
            const int j = blk * 16 + 2 * p;
            float2 f0 = unpk(h0[p]);
            float2 f1 = unpk(h1[p]);
            float A0 = fmaxf(f0.x + sb1[j],     0.f);
            float A1 = fmaxf(f0.y + sb1[j + 1], 0.f);
            float B0 = fmaxf(f1.x + sb1[j],     0.f);
            float B1 = fmaxf(f1.y + sb1[j + 1], 0.f);
            {
                u64 Pa = bcast2(A0), Pb = bcast2(B0);
                const ulonglong2* w2 = (const ulonglong2*)(sW2 + j * 32);
                #pragma unroll
                for (int q = 0; q < 8; q++) {
                    ulonglong2 wv = w2[q];
                    ffma2(r2a[2*q], Pa, wv.x); ffma2(r2a[2*q+1], Pa, wv.y);
                    ffma2(r2b[2*q], Pb, wv.x); ffma2(r2b[2*q+1], Pb, wv.y);
                }
            }
            {
                u64 Pa = bcast2(A1), Pb = bcast2(B1);
                const ulonglong2* w2 = (const ulonglong2*)(sW2 + (j + 1) * 32);
                #pragma unroll
                for (int q = 0; q < 8; q++) {
                    ulonglong2 wv = w2[q];
                    ffma2(r2a[2*q], Pa, wv.x); ffma2(r2a[2*q+1], Pa, wv.y);
                    ffma2(r2b[2*q], Pb, wv.x); ffma2(r2b[2*q+1], Pb, wv.y);
                }
            }
        }
    }

    // ---- store both batches' row t ----
    ulonglong2* o0 = (ulonglong2*)(gout + (gB0 * T + t) * DM);
    ulonglong2* o1 = (ulonglong2*)(gout + (gB1 * T + t) * DM);
    #pragma unroll
    for (int q = 0; q < 8; q++) {
        o0[q] = make_ulonglong2(r2a[2*q], r2a[2*q+1]);
        o1[q] = make_ulonglong2(r2b[2*q], r2b[2*q+1]);
    }
}

extern "C" void kernel_launch(void* const* d_in, const int* in_sizes, int n_in,
                              void* d_out, int out_size)
{
    const float* x   = (const float*)d_in[0];
    const float* Wq  = (const float*)d_in[1];
    const float* Wk  = (const float*)d_in[2];
    const float* Wv  = (const float*)d_in[3];
    const float* Wo  = (const float*)d_in[4];
    const float* bo  = (const float*)d_in[5];
    const float* W1  = (const float*)d_in[6];
    const float* b1  = (const float*)d_in[7];
    const float* W2  = (const float*)d_in[8];
    const float* b2  = (const float*)d_in[9];
    const float* g1  = (const float*)d_in[10];
    const float* be1 = (const float*)d_in[11];
    const float* g2  = (const float*)d_in[12];
    const float* be2 = (const float*)d_in[13];
    float* out = (float*)d_out;

    cudaFuncSetAttribute(block_kernel, cudaFuncAttributeMaxDynamicSharedMemorySize, SMEM_BYTES);
    block_kernel<<<Bsz / 2, 128, SMEM_BYTES>>>(x, Wq, Wk, Wv, Wo, bo, W1, b1, W2, b2,
                                               g1, be1, g2, be2, out);
}